// round 11
// baseline (speedup 1.0000x reference)
#include <cuda_runtime.h>
#include <cstdint>

// ---------- MUFU helpers ----------
__device__ __forceinline__ float ex2a(float x) { float r; asm("ex2.approx.f32 %0, %1;" : "=f"(r) : "f"(x)); return r; }
__device__ __forceinline__ float rcpa(float x) { float r; asm("rcp.approx.f32 %0, %1;" : "=f"(r) : "f"(x)); return r; }
#define TWO_LOG2E 2.8853900817779268f

// tanh with pre-scaled argument zs = 2*log2(e)*z:  tanh = 1 - 2/(2^zs + 1)
__device__ __forceinline__ float ftanh_s(float zs) {
    float r = rcpa(ex2a(zs) + 1.0f);
    return fmaf(r, -2.0f, 1.0f);
}

// polynomials in s = theta^2 (s <= ~2.6e-4 here; truncation <= 2.4e-14)
__device__ __forceinline__ float polyC(float s)  { return fmaf(s, fmaf(s,  1.0f/24.0f,  -0.5f),      1.0f); }
__device__ __forceinline__ float polyS(float s)  { return fmaf(s, fmaf(s,  1.0f/120.0f, -1.0f/6.0f), 1.0f); }
__device__ __forceinline__ float polySp(float s) { return fmaf(s, 1.0f/60.0f, -1.0f/6.0f); }

// ---------- volatile shared loads: use-site materialization, no CSE/hoist ----------
__device__ __forceinline__ float4 lds4(uint32_t addr) {
    float4 r;
    asm volatile("ld.shared.v4.f32 {%0, %1, %2, %3}, [%4];"
                 : "=f"(r.x), "=f"(r.y), "=f"(r.z), "=f"(r.w) : "r"(addr));
    return r;
}
__device__ __forceinline__ float lds1(uint32_t addr) {
    float r;
    asm volatile("ld.shared.f32 %0, [%1];" : "=f"(r) : "r"(addr));
    return r;
}

// ---------- shared weight bank layout (79 float4 = 316 floats) ----------
// f4 idx:  0.. 9 Jw1*c rows | 10..19 Vw1*c rows | 20..29 Vg rows (4*Vw2[k]*Vw1[k][j], UNscaled)
//         30..39 gw1*c rows | floats 160..171 Jb1*c | 172..183 gb1*c | 184..195 Vb1*c
//         f4 49..66 Jw2 (6 rows x 12 pad) | 67..75 gw2 (3 rows x 12 pad)
//         floats 304..307 gb2 | 308..313 Jb2        (c = 2*log2(e), folded for ex2-tanh)
#define W4(i4)  lds4(sb + 16*(i4))
#define WF(ifl) lds1(sb + 4*(ifl))

__device__ __forceinline__ float dot4b(float4 w, float q0, float q1, float q2, float q3, float b) {
    return fmaf(w.x, q0, fmaf(w.y, q1, fmaf(w.z, q2, fmaf(w.w, q3, b))));
}
__device__ __forceinline__ float dot10b(float4 a, float4 b4, float4 c, const float* h, float b) {
    float s = b;
    s = fmaf(a.x,  h[0], s); s = fmaf(a.y,  h[1], s); s = fmaf(a.z, h[2], s); s = fmaf(a.w, h[3], s);
    s = fmaf(b4.x, h[4], s); s = fmaf(b4.y, h[5], s); s = fmaf(b4.z, h[6], s); s = fmaf(b4.w, h[7], s);
    s = fmaf(c.x,  h[8], s); s = fmaf(c.y,  h[9], s);
    return s;
}

// dV/dq: d_j = sum_k Vg[k][j] * r_k(1-r_k), r_k = 1/(2^(zs_k)+1), zs pre-scaled
__device__ __forceinline__ void vgrad(uint32_t sb, float q0, float q1, float q2, float q3,
                                      float& d0, float& d1, float& d2, float& d3) {
    d0 = d1 = d2 = d3 = 0.0f;
#pragma unroll
    for (int k = 0; k < 10; k++) {
        float zs = dot4b(W4(10 + k), q0, q1, q2, q3, WF(184 + k));
        float r = rcpa(ex2a(zs) + 1.0f);
        float S = fmaf(-r, r, r);                 // r(1-r) = (1-tanh^2)/4
        float4 g = W4(20 + k);
        d0 = fmaf(g.x, S, d0); d1 = fmaf(g.y, S, d1);
        d2 = fmaf(g.z, S, d2); d3 = fmaf(g.w, S, d3);
    }
}

__global__ void __launch_bounds__(256)
step_kernel(const float4* __restrict__ xin, float4* __restrict__ xout, int B,
            const float* __restrict__ Jw1, const float* __restrict__ Jb1,
            const float* __restrict__ Jw2, const float* __restrict__ Jb2,
            const float* __restrict__ Vw1, const float* __restrict__ Vb1,
            const float* __restrict__ Vw2,
            const float* __restrict__ gw1, const float* __restrict__ gb1,
            const float* __restrict__ gw2, const float* __restrict__ gb2) {
    __shared__ float4 sK[79];
    float* sF = (float*)sK;

    // ---- per-block cooperative weight fold (R7-proven math) ----
    for (int t = threadIdx.x; t < 316; t += 256) {
        float v = 0.0f;
        if      (t < 40)  v = TWO_LOG2E * Jw1[t];
        else if (t < 80)  v = TWO_LOG2E * Vw1[t - 40];
        else if (t < 120) { int j = t - 80; v = 4.0f * Vw2[j >> 2] * Vw1[j]; }
        else if (t < 160) v = TWO_LOG2E * gw1[t - 120];
        else if (t < 172) { int j = t - 160; v = (j < 10) ? TWO_LOG2E * Jb1[j] : 0.0f; }
        else if (t < 184) { int j = t - 172; v = (j < 10) ? TWO_LOG2E * gb1[j] : 0.0f; }
        else if (t < 196) { int j = t - 184; v = (j < 10) ? TWO_LOG2E * Vb1[j] : 0.0f; }
        else if (t < 268) { int j = t - 196; int r = j / 12, c = j % 12; v = (c < 10) ? Jw2[r * 10 + c] : 0.0f; }
        else if (t < 304) { int j = t - 268; int r = j / 12, c = j % 12; v = (c < 10) ? gw2[r * 10 + c] : 0.0f; }
        else if (t < 308) { int j = t - 304; v = (j < 3) ? gb2[j] : 0.0f; }
        else              { int j = t - 308; v = (j < 6) ? Jb2[j] : 0.0f; }
        sF[t] = v;
    }
    __syncthreads();

    uint32_t sb;
    asm("{ .reg .u64 t; cvta.to.shared.u64 t, %1; cvt.u32.u64 %0, t; }" : "=r"(sb) : "l"(sK));

    int i = blockIdx.x * 256 + threadIdx.x;
    if (i >= B) return;

    float4 a = xin[2*i];
    float4 b = xin[2*i + 1];
    float q0 = a.x, q1 = a.y, q2 = a.z, q3 = a.w;
    float w0 = b.x, w1 = b.y, w2 = b.z, u = b.w;

    // ---- J MLP -> l[6] ----
    float hd[10];
#pragma unroll
    for (int k = 0; k < 10; k++)
        hd[k] = ftanh_s(dot4b(W4(k), q0, q1, q2, q3, WF(160 + k)));
    float l[6];
#pragma unroll
    for (int r6 = 0; r6 < 6; r6++)
        l[r6] = dot10b(W4(49 + 3*r6), W4(50 + 3*r6), W4(51 + 3*r6), hd, WF(308 + r6));

    // ---- M = L L^T + 0.01 I ----
    float M00 = fmaf(l[0], l[0], 0.01f);
    float M01 = l[0]*l[1];
    float M02 = l[0]*l[3];
    float M11 = fmaf(l[2], l[2], fmaf(l[1], l[1], 0.01f));
    float M12 = fmaf(l[2], l[4], l[1]*l[3]);
    float M22 = fmaf(l[5], l[5], fmaf(l[4], l[4], fmaf(l[3], l[3], 0.01f)));

    // ---- J = inv(M) via adjugate ----
    float c00 = M11*M22 - M12*M12;
    float c01 = M02*M12 - M01*M22;
    float c02 = M01*M12 - M02*M11;
    float c11 = M00*M22 - M02*M02;
    float c12 = M01*M02 - M00*M12;
    float c22 = M00*M11 - M01*M01;
    float det = fmaf(M02, c02, fmaf(M01, c01, M00*c00));
    float id  = rcpa(det);
    float J00 = c00*id, J01 = c01*id, J02 = c02*id;
    float J11 = c11*id, J12 = c12*id, J22 = c22*id;

    // ---- g MLP -> fk ----
    float fk0, fk1, fk2;
    {
        float hg[10];
#pragma unroll
        for (int k = 0; k < 10; k++)
            hg[k] = ftanh_s(dot4b(W4(30 + k), q0, q1, q2, q3, WF(172 + k)));
        float g0 = dot10b(W4(67), W4(68), W4(69), hg, WF(304));
        float g1 = dot10b(W4(70), W4(71), W4(72), hg, WF(305));
        float g2 = dot10b(W4(73), W4(74), W4(75), hg, WF(306));
        float cu = 0.005f * u;
        fk0 = cu*g0; fk1 = cu*g1; fk2 = cu*g2;
    }

    // ---- dV at qk, Hd = H(qk) dV ----
    float dv0, dv1, dv2, dv3;
    vgrad(sb, q0, q1, q2, q3, dv0, dv1, dv2, dv3);
    float Hd0 = fmaf(q1, dv0, fmaf(q0, dv1, q3*dv2 - q2*dv3));
    float Hd1 = fmaf(q2, dv0, fmaf(q0, dv2, q1*dv3 - q3*dv1));
    float Hd2 = fmaf(q3, dv0, fmaf(q0, dv3, q2*dv1 - q1*dv2));

    // ---- NR = -RHS = 0.005*(J w) + 0.0025*fk - 1.25e-5*Hd ----
    float Jw0 = fmaf(J02, w2, fmaf(J01, w1, J00*w0));
    float Jw1v = fmaf(J12, w2, fmaf(J11, w1, J01*w0));
    float Jw2v = fmaf(J22, w2, fmaf(J12, w1, J02*w0));
    float NR0 = fmaf(0.005f, Jw0,  fmaf(0.0025f, fk0, -1.25e-5f*Hd0));
    float NR1 = fmaf(0.005f, Jw1v, fmaf(0.0025f, fk1, -1.25e-5f*Hd1));
    float NR2 = fmaf(0.005f, Jw2v, fmaf(0.0025f, fk2, -1.25e-5f*Hd2));

    // ---- Newton step 1 (xi=0 exact): xi1 = M*NR ----
    float xi0 = fmaf(M02, NR2, fmaf(M01, NR1, M00*NR0));
    float xi1 = fmaf(M12, NR2, fmaf(M11, NR1, M01*NR0));
    float xi2 = fmaf(M22, NR2, fmaf(M12, NR1, M02*NR0));

    // ---- Newton steps 2..4: FULL exact Jacobian, poly trig in s ----
#pragma unroll
    for (int it = 0; it < 3; it++) {
        float s2v = fmaf(xi2, xi2, fmaf(xi1, xi1, xi0*xi0));
        float cs = polyC(s2v);
        float si = polyS(s2v);
        float Sp = polySp(s2v);
        float a1  = -cs*si;
        float ns2 = -si*si;
        float al  = fmaf(si, si, -2.0f*cs*Sp);
        float ga  = -4.0f*si*Sp;

        float Jx0 = fmaf(J02, xi2, fmaf(J01, xi1, J00*xi0));
        float Jx1 = fmaf(J12, xi2, fmaf(J11, xi1, J01*xi0));
        float Jx2 = fmaf(J22, xi2, fmaf(J12, xi1, J02*xi0));
        float cx0 = xi1*Jx2 - xi2*Jx1;
        float cx1 = xi2*Jx0 - xi0*Jx2;
        float cx2 = xi0*Jx1 - xi1*Jx0;

        float r0 = fmaf(a1, Jx0, fmaf(ns2, cx0, NR0));
        float r1 = fmaf(a1, Jx1, fmaf(ns2, cx1, NR1));
        float r2 = fmaf(a1, Jx2, fmaf(ns2, cx2, NR2));

        float w30 = fmaf(ga, cx0, al*Jx0);
        float w31 = fmaf(ga, cx1, al*Jx1);
        float w32 = fmaf(ga, cx2, al*Jx2);

        float xJ00 = xi1*J02 - xi2*J01;
        float xJ01 = xi2*J00 - xi0*J02;
        float xJ02 = xi0*J01 - xi1*J00;
        float xJ10 = xi1*J12 - xi2*J11;
        float xJ11 = xi2*J01 - xi0*J12;
        float xJ12 = xi0*J11 - xi1*J01;
        float xJ20 = xi1*J22 - xi2*J12;
        float xJ21 = xi2*J02 - xi0*J22;
        float xJ22 = xi0*J12 - xi1*J02;
        float T00 = xJ00;       float T01 = xJ01 - Jx2; float T02 = xJ02 + Jx1;
        float T10 = xJ10 + Jx2; float T11 = xJ11;       float T12 = xJ12 - Jx0;
        float T20 = xJ20 - Jx1; float T21 = xJ21 + Jx0; float T22 = xJ22;

        float A00 = fmaf(xi0, w30, fmaf(a1, J00, ns2*T00));
        float A10 = fmaf(xi0, w31, fmaf(a1, J01, ns2*T01));
        float A20 = fmaf(xi0, w32, fmaf(a1, J02, ns2*T02));
        float A01 = fmaf(xi1, w30, fmaf(a1, J01, ns2*T10));
        float A11 = fmaf(xi1, w31, fmaf(a1, J11, ns2*T11));
        float A21 = fmaf(xi1, w32, fmaf(a1, J12, ns2*T12));
        float A02 = fmaf(xi2, w30, fmaf(a1, J02, ns2*T20));
        float A12 = fmaf(xi2, w31, fmaf(a1, J12, ns2*T21));
        float A22 = fmaf(xi2, w32, fmaf(a1, J22, ns2*T22));

        // Cramer solve A d = r
        float cvt0 = A11*A22 - A21*A12;
        float cvt1 = A21*A02 - A01*A22;
        float cvt2 = A01*A12 - A11*A02;
        float ctu0 = A12*A20 - A22*A10;
        float ctu1 = A22*A00 - A02*A20;
        float ctu2 = A02*A10 - A12*A00;
        float cuv0 = A10*A21 - A20*A11;
        float cuv1 = A20*A01 - A00*A21;
        float cuv2 = A00*A11 - A10*A01;
        float dt  = fmaf(A20, cvt2, fmaf(A10, cvt1, A00*cvt0));
        float nid = -rcpa(dt);
        float n0 = fmaf(r2, cvt2, fmaf(r1, cvt1, r0*cvt0));
        float n1 = fmaf(r2, ctu2, fmaf(r1, ctu1, r0*ctu0));
        float n2 = fmaf(r2, cuv2, fmaf(r1, cuv1, r0*cuv0));
        xi0 = fmaf(n0, nid, xi0);
        xi1 = fmaf(n1, nid, xi1);
        xi2 = fmaf(n2, nid, xi2);
    }

    // ---- e = quat_exp(xi): poly ----
    float s  = fmaf(xi2, xi2, fmaf(xi1, xi1, xi0*xi0));
    float e0 = polyC(s);
    float sc = polyS(s);
    float e1 = xi0*sc, e2 = xi1*sc, e3 = xi2*sc;

    // ---- qn = quat_mul(qk, e) ----
    float qn0 = q0*e0 - fmaf(q3, e3, fmaf(q2, e2, q1*e1));
    float qn1 = fmaf(q0, e1, fmaf(q1, e0, q2*e3 - q3*e2));
    float qn2 = fmaf(q0, e2, fmaf(q2, e0, q3*e1 - q1*e3));
    float qn3 = fmaf(q0, e3, fmaf(q3, e0, q1*e2 - q2*e1));

    // ---- dV at qn ----
    float dn0, dn1, dn2, dn3;
    vgrad(sb, qn0, qn1, qn2, qn3, dn0, dn1, dn2, dn3);

    // ---- qq = quat_mul(conj(qk), qn) ----
    float qq0 = fmaf(q3, qn3, fmaf(q2, qn2, fmaf(q1, qn1, q0*qn0)));
    float qq1 = fmaf(q0, qn1, (q3*qn2 - q1*qn0) - q2*qn3);
    float qq2 = fmaf(q0, qn2, (q1*qn3 - q2*qn0) - q3*qn1);
    float qq3 = fmaf(q0, qn3, (q2*qn1 - q1*qn2) - q3*qn0);

    // ---- y = J qq_v ; G = qq0*y - qq_v x y ----
    float y0 = fmaf(J02, qq3, fmaf(J01, qq2, J00*qq1));
    float y1 = fmaf(J12, qq3, fmaf(J11, qq2, J01*qq1));
    float y2 = fmaf(J22, qq3, fmaf(J12, qq2, J02*qq1));
    float G0 = fmaf(qq0, y0, qq3*y1 - qq2*y2);
    float G1 = fmaf(qq0, y1, qq1*y2 - qq3*y0);
    float G2 = fmaf(qq0, y2, qq2*y0 - qq1*y1);

    // ---- Hn = H(qn) dn ----
    float Hn0 = fmaf(qn1, dn0, fmaf(qn0, dn1, qn3*dn2 - qn2*dn3));
    float Hn1 = fmaf(qn2, dn0, fmaf(qn0, dn2, qn1*dn3 - qn3*dn1));
    float Hn2 = fmaf(qn3, dn0, fmaf(qn0, dn3, qn2*dn1 - qn1*dn2));

    // ---- pn = 400 G - 0.005 Hn + fk ; wn = 0.5 M pn ----
    float pn0 = fmaf(400.0f, G0, fmaf(-0.005f, Hn0, fk0));
    float pn1 = fmaf(400.0f, G1, fmaf(-0.005f, Hn1, fk1));
    float pn2 = fmaf(400.0f, G2, fmaf(-0.005f, Hn2, fk2));
    float wn0 = 0.5f*fmaf(M02, pn2, fmaf(M01, pn1, M00*pn0));
    float wn1 = 0.5f*fmaf(M12, pn2, fmaf(M11, pn1, M01*pn0));
    float wn2 = 0.5f*fmaf(M22, pn2, fmaf(M12, pn1, M02*pn0));

    xout[2*i]     = make_float4(qn0, qn1, qn2, qn3);
    xout[2*i + 1] = make_float4(wn0, wn1, wn2, u);
}

extern "C" void kernel_launch(void* const* d_in, const int* in_sizes, int n_in,
                              void* d_out, int out_size) {
    int B = in_sizes[0] / 8;
    step_kernel<<<(B + 255) / 256, 256>>>(
        (const float4*)d_in[0], (float4*)d_out, B,
        (const float*)d_in[1],  (const float*)d_in[2],  (const float*)d_in[3],
        (const float*)d_in[4],  (const float*)d_in[5],  (const float*)d_in[6],
        (const float*)d_in[7],
        (const float*)d_in[9],  (const float*)d_in[10], (const float*)d_in[11],
        (const float*)d_in[12]);
}

// round 12
// speedup vs baseline: 1.5792x; 1.5792x over previous
#include <cuda_runtime.h>

// ---------- MUFU helpers ----------
__device__ __forceinline__ float ex2a(float x) { float r; asm("ex2.approx.f32 %0, %1;" : "=f"(r) : "f"(x)); return r; }
__device__ __forceinline__ float rcpa(float x) { float r; asm("rcp.approx.f32 %0, %1;" : "=f"(r) : "f"(x)); return r; }
#define TWO_LOG2E 2.8853900817779268f

// tanh with pre-scaled argument zs = 2*log2(e)*z:  tanh = 1 - 2/(2^zs + 1)
__device__ __forceinline__ float ftanh_s(float zs) {
    float r = rcpa(ex2a(zs) + 1.0f);
    return fmaf(r, -2.0f, 1.0f);
}

// polynomials in s = theta^2 (s <= ~2.6e-4 here; truncation <= 2.4e-14)
__device__ __forceinline__ float polyC(float s)  { return fmaf(s, fmaf(s,  1.0f/24.0f,  -0.5f),      1.0f); }
__device__ __forceinline__ float polyS(float s)  { return fmaf(s, fmaf(s,  1.0f/120.0f, -1.0f/6.0f), 1.0f); }
__device__ __forceinline__ float polySp(float s) { return fmaf(s, 1.0f/60.0f, -1.0f/6.0f); }

// ---------- constant bank: float4-padded layout (79 float4 = 316 floats) ----------
// f4 idx:  0.. 9 Jw1*c rows | 10..19 Vw1*c rows | 20..29 Vg rows (4*Vw2[k]*Vw1[k][j], UNscaled)
//         30..39 gw1*c rows | floats 160..171 Jb1*c | 172..183 gb1*c | 184..195 Vb1*c
//         f4 49..66 Jw2 (6 rows x 12 pad) | 67..75 gw2 (3 rows x 12 pad)
//         floats 304..307 gb2 | 308..313 Jb2        (c = 2*log2(e), folded for ex2-tanh)
__constant__ float4 cK[79];

// setup writes the folded bank DIRECTLY into cK's backing store (address passed in),
// eliminating the staging buffer + memcpy graph node. Values are identical on every
// call (idempotent), and step_kernel's constant-cache lines are cold at first touch.
__global__ void setup_kernel(float* dst,
                             const float* Jw1, const float* Jb1, const float* Jw2, const float* Jb2,
                             const float* Vw1, const float* Vb1, const float* Vw2,
                             const float* gw1, const float* gb1, const float* gw2, const float* gb2) {
    int i = threadIdx.x;
    if (i >= 316) return;
    float v = 0.0f;
    if      (i < 40)  v = TWO_LOG2E * Jw1[i];
    else if (i < 80)  v = TWO_LOG2E * Vw1[i - 40];
    else if (i < 120) { int t = i - 80; v = 4.0f * Vw2[t >> 2] * Vw1[t]; }
    else if (i < 160) v = TWO_LOG2E * gw1[i - 120];
    else if (i < 172) { int j = i - 160; v = (j < 10) ? TWO_LOG2E * Jb1[j] : 0.0f; }
    else if (i < 184) { int j = i - 172; v = (j < 10) ? TWO_LOG2E * gb1[j] : 0.0f; }
    else if (i < 196) { int j = i - 184; v = (j < 10) ? TWO_LOG2E * Vb1[j] : 0.0f; }
    else if (i < 268) { int t = i - 196; int r = t / 12, c = t % 12; v = (c < 10) ? Jw2[r * 10 + c] : 0.0f; }
    else if (i < 304) { int t = i - 268; int r = t / 12, c = t % 12; v = (c < 10) ? gw2[r * 10 + c] : 0.0f; }
    else if (i < 308) { int j = i - 304; v = (j < 3) ? gb2[j] : 0.0f; }
    else              { int j = i - 308; v = (j < 6) ? Jb2[j] : 0.0f; }
    dst[i] = v;
}

__device__ __forceinline__ float dot4b(float4 w, float q0, float q1, float q2, float q3, float b) {
    return fmaf(w.x, q0, fmaf(w.y, q1, fmaf(w.z, q2, fmaf(w.w, q3, b))));
}
__device__ __forceinline__ float dot10b(float4 a, float4 b4, float4 c, const float* h, float b) {
    float s = b;
    s = fmaf(a.x,  h[0], s); s = fmaf(a.y,  h[1], s); s = fmaf(a.z, h[2], s); s = fmaf(a.w, h[3], s);
    s = fmaf(b4.x, h[4], s); s = fmaf(b4.y, h[5], s); s = fmaf(b4.z, h[6], s); s = fmaf(b4.w, h[7], s);
    s = fmaf(c.x,  h[8], s); s = fmaf(c.y,  h[9], s);
    return s;
}

#define CF(i) (((const float*)cK)[i])

// dV/dq: d_j = sum_k Vg[k][j] * r_k(1-r_k), r_k = 1/(2^(zs_k)+1), zs pre-scaled
__device__ __forceinline__ void vgrad(float q0, float q1, float q2, float q3,
                                      float& d0, float& d1, float& d2, float& d3) {
    d0 = d1 = d2 = d3 = 0.0f;
#pragma unroll
    for (int k = 0; k < 10; k++) {
        float zs = dot4b(cK[10 + k], q0, q1, q2, q3, CF(184 + k));
        float r = rcpa(ex2a(zs) + 1.0f);
        float S = fmaf(-r, r, r);                 // r(1-r) = (1-tanh^2)/4
        float4 g = cK[20 + k];
        d0 = fmaf(g.x, S, d0); d1 = fmaf(g.y, S, d1);
        d2 = fmaf(g.z, S, d2); d3 = fmaf(g.w, S, d3);
    }
}

__global__ void __launch_bounds__(256)
step_kernel(const float4* __restrict__ xin, float4* __restrict__ xout, int B) {
    int i = blockIdx.x * 256 + threadIdx.x;
    if (i >= B) return;

    float4 a = xin[2*i];
    float4 b = xin[2*i + 1];
    float q0 = a.x, q1 = a.y, q2 = a.z, q3 = a.w;
    float w0 = b.x, w1 = b.y, w2 = b.z, u = b.w;

    // ---- J MLP -> l[6] ----
    float hd[10];
#pragma unroll
    for (int k = 0; k < 10; k++)
        hd[k] = ftanh_s(dot4b(cK[k], q0, q1, q2, q3, CF(160 + k)));
    float l[6];
#pragma unroll
    for (int r6 = 0; r6 < 6; r6++)
        l[r6] = dot10b(cK[49 + 3*r6], cK[50 + 3*r6], cK[51 + 3*r6], hd, CF(308 + r6));

    // ---- M = L L^T + 0.01 I ----
    float M00 = fmaf(l[0], l[0], 0.01f);
    float M01 = l[0]*l[1];
    float M02 = l[0]*l[3];
    float M11 = fmaf(l[2], l[2], fmaf(l[1], l[1], 0.01f));
    float M12 = fmaf(l[2], l[4], l[1]*l[3]);
    float M22 = fmaf(l[5], l[5], fmaf(l[4], l[4], fmaf(l[3], l[3], 0.01f)));

    // ---- J = inv(M) via adjugate ----
    float c00 = M11*M22 - M12*M12;
    float c01 = M02*M12 - M01*M22;
    float c02 = M01*M12 - M02*M11;
    float c11 = M00*M22 - M02*M02;
    float c12 = M01*M02 - M00*M12;
    float c22 = M00*M11 - M01*M01;
    float det = fmaf(M02, c02, fmaf(M01, c01, M00*c00));
    float id  = rcpa(det);
    float J00 = c00*id, J01 = c01*id, J02 = c02*id;
    float J11 = c11*id, J12 = c12*id, J22 = c22*id;

    // ---- g MLP -> fk ----
    float fk0, fk1, fk2;
    {
        float hg[10];
#pragma unroll
        for (int k = 0; k < 10; k++)
            hg[k] = ftanh_s(dot4b(cK[30 + k], q0, q1, q2, q3, CF(172 + k)));
        float g0 = dot10b(cK[67], cK[68], cK[69], hg, CF(304));
        float g1 = dot10b(cK[70], cK[71], cK[72], hg, CF(305));
        float g2 = dot10b(cK[73], cK[74], cK[75], hg, CF(306));
        float cu = 0.005f * u;
        fk0 = cu*g0; fk1 = cu*g1; fk2 = cu*g2;
    }

    // ---- dV at qk, Hd = H(qk) dV ----
    float dv0, dv1, dv2, dv3;
    vgrad(q0, q1, q2, q3, dv0, dv1, dv2, dv3);
    float Hd0 = fmaf(q1, dv0, fmaf(q0, dv1, q3*dv2 - q2*dv3));
    float Hd1 = fmaf(q2, dv0, fmaf(q0, dv2, q1*dv3 - q3*dv1));
    float Hd2 = fmaf(q3, dv0, fmaf(q0, dv3, q2*dv1 - q1*dv2));

    // ---- NR = -RHS = 0.005*(J w) + 0.0025*fk - 1.25e-5*Hd  (pk=2Jw folded) ----
    float Jw0 = fmaf(J02, w2, fmaf(J01, w1, J00*w0));
    float Jw1v = fmaf(J12, w2, fmaf(J11, w1, J01*w0));
    float Jw2v = fmaf(J22, w2, fmaf(J12, w1, J02*w0));
    float NR0 = fmaf(0.005f, Jw0,  fmaf(0.0025f, fk0, -1.25e-5f*Hd0));
    float NR1 = fmaf(0.005f, Jw1v, fmaf(0.0025f, fk1, -1.25e-5f*Hd1));
    float NR2 = fmaf(0.005f, Jw2v, fmaf(0.0025f, fk2, -1.25e-5f*Hd2));

    // ---- Newton step 1 (xi=0 exact): jac(0)=-J, inverse=-M => xi1 = M*NR ----
    float xi0 = fmaf(M02, NR2, fmaf(M01, NR1, M00*NR0));
    float xi1 = fmaf(M12, NR2, fmaf(M11, NR1, M01*NR0));
    float xi2 = fmaf(M22, NR2, fmaf(M12, NR1, M02*NR0));

    // ---- Newton steps 2..4: FULL exact Jacobian, poly trig in s (R6-proven) ----
#pragma unroll
    for (int it = 0; it < 3; it++) {
        float s2v = fmaf(xi2, xi2, fmaf(xi1, xi1, xi0*xi0));
        float cs = polyC(s2v);
        float si = polyS(s2v);
        float Sp = polySp(s2v);
        float a1  = -cs*si;
        float ns2 = -si*si;
        float al  = fmaf(si, si, -2.0f*cs*Sp);
        float ga  = -4.0f*si*Sp;

        float Jx0 = fmaf(J02, xi2, fmaf(J01, xi1, J00*xi0));
        float Jx1 = fmaf(J12, xi2, fmaf(J11, xi1, J01*xi0));
        float Jx2 = fmaf(J22, xi2, fmaf(J12, xi1, J02*xi0));
        float cx0 = xi1*Jx2 - xi2*Jx1;
        float cx1 = xi2*Jx0 - xi0*Jx2;
        float cx2 = xi0*Jx1 - xi1*Jx0;

        float r0 = fmaf(a1, Jx0, fmaf(ns2, cx0, NR0));
        float r1 = fmaf(a1, Jx1, fmaf(ns2, cx1, NR1));
        float r2 = fmaf(a1, Jx2, fmaf(ns2, cx2, NR2));

        float w30 = fmaf(ga, cx0, al*Jx0);
        float w31 = fmaf(ga, cx1, al*Jx1);
        float w32 = fmaf(ga, cx2, al*Jx2);

        float xJ00 = xi1*J02 - xi2*J01;
        float xJ01 = xi2*J00 - xi0*J02;
        float xJ02 = xi0*J01 - xi1*J00;
        float xJ10 = xi1*J12 - xi2*J11;
        float xJ11 = xi2*J01 - xi0*J12;
        float xJ12 = xi0*J11 - xi1*J01;
        float xJ20 = xi1*J22 - xi2*J12;
        float xJ21 = xi2*J02 - xi0*J22;
        float xJ22 = xi0*J12 - xi1*J02;
        float T00 = xJ00;       float T01 = xJ01 - Jx2; float T02 = xJ02 + Jx1;
        float T10 = xJ10 + Jx2; float T11 = xJ11;       float T12 = xJ12 - Jx0;
        float T20 = xJ20 - Jx1; float T21 = xJ21 + Jx0; float T22 = xJ22;

        float A00 = fmaf(xi0, w30, fmaf(a1, J00, ns2*T00));
        float A10 = fmaf(xi0, w31, fmaf(a1, J01, ns2*T01));
        float A20 = fmaf(xi0, w32, fmaf(a1, J02, ns2*T02));
        float A01 = fmaf(xi1, w30, fmaf(a1, J01, ns2*T10));
        float A11 = fmaf(xi1, w31, fmaf(a1, J11, ns2*T11));
        float A21 = fmaf(xi1, w32, fmaf(a1, J12, ns2*T12));
        float A02 = fmaf(xi2, w30, fmaf(a1, J02, ns2*T20));
        float A12 = fmaf(xi2, w31, fmaf(a1, J12, ns2*T21));
        float A22 = fmaf(xi2, w32, fmaf(a1, J22, ns2*T22));

        // Cramer solve A d = r
        float cvt0 = A11*A22 - A21*A12;
        float cvt1 = A21*A02 - A01*A22;
        float cvt2 = A01*A12 - A11*A02;
        float ctu0 = A12*A20 - A22*A10;
        float ctu1 = A22*A00 - A02*A20;
        float ctu2 = A02*A10 - A12*A00;
        float cuv0 = A10*A21 - A20*A11;
        float cuv1 = A20*A01 - A00*A21;
        float cuv2 = A00*A11 - A10*A01;
        float dt  = fmaf(A20, cvt2, fmaf(A10, cvt1, A00*cvt0));
        float nid = -rcpa(dt);
        float n0 = fmaf(r2, cvt2, fmaf(r1, cvt1, r0*cvt0));
        float n1 = fmaf(r2, ctu2, fmaf(r1, ctu1, r0*ctu0));
        float n2 = fmaf(r2, cuv2, fmaf(r1, cuv1, r0*cuv0));
        xi0 = fmaf(n0, nid, xi0);
        xi1 = fmaf(n1, nid, xi1);
        xi2 = fmaf(n2, nid, xi2);
    }

    // ---- e = quat_exp(xi): poly ----
    float s  = fmaf(xi2, xi2, fmaf(xi1, xi1, xi0*xi0));
    float e0 = polyC(s);
    float sc = polyS(s);
    float e1 = xi0*sc, e2 = xi1*sc, e3 = xi2*sc;

    // ---- qn = quat_mul(qk, e) ----
    float qn0 = q0*e0 - fmaf(q3, e3, fmaf(q2, e2, q1*e1));
    float qn1 = fmaf(q0, e1, fmaf(q1, e0, q2*e3 - q3*e2));
    float qn2 = fmaf(q0, e2, fmaf(q2, e0, q3*e1 - q1*e3));
    float qn3 = fmaf(q0, e3, fmaf(q3, e0, q1*e2 - q2*e1));

    // ---- dV at qn ----
    float dn0, dn1, dn2, dn3;
    vgrad(qn0, qn1, qn2, qn3, dn0, dn1, dn2, dn3);

    // ---- qq = quat_mul(conj(qk), qn) ----
    float qq0 = fmaf(q3, qn3, fmaf(q2, qn2, fmaf(q1, qn1, q0*qn0)));
    float qq1 = fmaf(q0, qn1, (q3*qn2 - q1*qn0) - q2*qn3);
    float qq2 = fmaf(q0, qn2, (q1*qn3 - q2*qn0) - q3*qn1);
    float qq3 = fmaf(q0, qn3, (q2*qn1 - q1*qn2) - q3*qn0);

    // ---- y = J qq_v ; G = qq0*y - qq_v x y ----
    float y0 = fmaf(J02, qq3, fmaf(J01, qq2, J00*qq1));
    float y1 = fmaf(J12, qq3, fmaf(J11, qq2, J01*qq1));
    float y2 = fmaf(J22, qq3, fmaf(J12, qq2, J02*qq1));
    float G0 = fmaf(qq0, y0, qq3*y1 - qq2*y2);
    float G1 = fmaf(qq0, y1, qq1*y2 - qq3*y0);
    float G2 = fmaf(qq0, y2, qq2*y0 - qq1*y1);

    // ---- Hn = H(qn) dn ----
    float Hn0 = fmaf(qn1, dn0, fmaf(qn0, dn1, qn3*dn2 - qn2*dn3));
    float Hn1 = fmaf(qn2, dn0, fmaf(qn0, dn2, qn1*dn3 - qn3*dn1));
    float Hn2 = fmaf(qn3, dn0, fmaf(qn0, dn3, qn2*dn1 - qn1*dn2));

    // ---- pn = 400 G - 0.005 Hn + fk ; wn = 0.5 M pn ----
    float pn0 = fmaf(400.0f, G0, fmaf(-0.005f, Hn0, fk0));
    float pn1 = fmaf(400.0f, G1, fmaf(-0.005f, Hn1, fk1));
    float pn2 = fmaf(400.0f, G2, fmaf(-0.005f, Hn2, fk2));
    float wn0 = 0.5f*fmaf(M02, pn2, fmaf(M01, pn1, M00*pn0));
    float wn1 = 0.5f*fmaf(M12, pn2, fmaf(M11, pn1, M01*pn0));
    float wn2 = 0.5f*fmaf(M22, pn2, fmaf(M12, pn1, M02*pn0));

    xout[2*i]     = make_float4(qn0, qn1, qn2, qn3);
    xout[2*i + 1] = make_float4(wn0, wn1, wn2, u);
}

extern "C" void kernel_launch(void* const* d_in, const int* in_sizes, int n_in,
                              void* d_out, int out_size) {
    // address of cK's backing store (pure query; no allocation)
    void* ck_ptr = nullptr;
    cudaGetSymbolAddress(&ck_ptr, cK);

    setup_kernel<<<1, 320>>>((float*)ck_ptr,
        (const float*)d_in[1],  (const float*)d_in[2],  (const float*)d_in[3],
        (const float*)d_in[4],  (const float*)d_in[5],  (const float*)d_in[6],
        (const float*)d_in[7],
        (const float*)d_in[9],  (const float*)d_in[10], (const float*)d_in[11],
        (const float*)d_in[12]);

    int B = in_sizes[0] / 8;
    step_kernel<<<(B + 255) / 256, 256>>>((const float4*)d_in[0], (float4*)d_out, B);
}